// round 14
// baseline (speedup 1.0000x reference)
#include <cuda_runtime.h>
#include <cstdint>

// VoxelHashTable — counting-sort-clustered gather + PDL-overlapped launches.
//
// R8: gather at byte-floor (184us @ 6.5TB/s); pre-pass work <10us but 3 extra
//     launches cost ~31us total.
// R9/R10: persistent-kernel fusion FAILED (grid barriers + occupancy loss).
// This round: keep the 4-kernel dependency chain, hide the launch gaps with
// Programmatic Dependent Launch: downstream kernels launch with the
// ProgrammaticStreamSerialization attribute and self-gate via
// cudaGridDependencySynchronize(); producers trigger after their last write.
// Cross-replay: hash_hist is a NORMAL launch -> serializes against the
// previous replay's gather before scratch is overwritten.
//
// Also: scatter writes packed int2{qi, vidx} so gather needs one load, not
// perm -> dependent vidx (one fewer L2 round-trip on the critical chain).

#define FEATURE_DIM 768
#define VEC4_PER_ROW (FEATURE_DIM / 4)     // 192
#define V4_PER_LANE (VEC4_PER_ROW / 32)    // 6
#define TABLE_MASK ((1u << 20) - 1u)
#define THREADS 256
#define M_MAX (1 << 18)                    // 262144 queries
#define BUCKET_SHIFT 7                     // 128 voxel rows per bucket
#define NBINS 8192

__device__ int  g_vidx[M_MAX];
__device__ int  g_rank[M_MAX];
__device__ int2 g_sorted[M_MAX];           // {qi, vidx} in bin-sorted order
__device__ int  g_hist[NBINS];             // zero-init at load; scan re-zeroes
__device__ int  g_off[NBINS];

// 1 query/thread: hash, table lookup, bin rank via atomicAdd return.
__global__ void __launch_bounds__(256) hash_hist(
    const float* __restrict__ query_pts,   // [M, 3]
    const int* __restrict__ buf,           // [2^20], int32
    int total_voxels)
{
    const int qi = blockIdx.x * blockDim.x + threadIdx.x;

    const float px = __ldg(&query_pts[qi * 3 + 0]);
    const float py = __ldg(&query_pts[qi * 3 + 1]);
    const float pz = __ldg(&query_pts[qi * 3 + 2]);

    // f32 division by 0.1f required for bit-exact floor(q / RES).
    const long long gx = (long long)floorf(px / 0.1f);
    const long long gy = (long long)floorf(py / 0.1f);
    const long long gz = (long long)floorf(pz / 0.1f);

    // Products ~1e10 overflow int32 -> 64-bit. Pow2 mod == AND (neg-safe).
    const unsigned h = (unsigned)((gx * 73856093LL + gy * 19349669LL
                                   + gz * 83492791LL) & (long long)TABLE_MASK);

    int v = __ldg(&buf[h]);
    if (v >= total_voxels) v = -1;

    const int bin = (v >= 0) ? (v >> BUCKET_SHIFT) : (NBINS - 1);
    g_vidx[qi] = v;
    g_rank[qi] = atomicAdd(&g_hist[bin], 1);   // rank within bin

    cudaTriggerProgrammaticLaunchCompletion();
}

// Exclusive prefix sum over NBINS=8192 bins -> g_off. Single 1024-thread
// block. Also re-zeroes g_hist so the next graph replay starts clean.
__global__ void __launch_bounds__(1024) scan_hist()
{
    cudaGridDependencySynchronize();       // wait for hash_hist's writes

    const int tid  = threadIdx.x;
    const int lane = tid & 31;
    const int warp = tid >> 5;

    int v[NBINS / 1024];
    int sum = 0;
    #pragma unroll
    for (int i = 0; i < NBINS / 1024; i++) {
        v[i] = g_hist[tid * (NBINS / 1024) + i];
        g_hist[tid * (NBINS / 1024) + i] = 0;   // reset for next replay
        sum += v[i];
    }

    int x = sum;
    #pragma unroll
    for (int d = 1; d < 32; d <<= 1) {
        int y = __shfl_up_sync(0xFFFFFFFFu, x, d);
        if (lane >= d) x += y;
    }

    __shared__ int wsum[32];
    if (lane == 31) wsum[warp] = x;
    __syncthreads();
    if (warp == 0) {
        int w = wsum[lane];
        #pragma unroll
        for (int d = 1; d < 32; d <<= 1) {
            int y = __shfl_up_sync(0xFFFFFFFFu, w, d);
            if (lane >= d) w += y;
        }
        wsum[lane] = w;
    }
    __syncthreads();

    int excl = x - sum + (warp > 0 ? wsum[warp - 1] : 0);
    #pragma unroll
    for (int i = 0; i < NBINS / 1024; i++) {
        g_off[tid * (NBINS / 1024) + i] = excl;
        excl += v[i];
    }

    cudaTriggerProgrammaticLaunchCompletion();
}

// Atomic-free scatter: pos = off[bin] + rank; writes packed {qi, vidx}.
__global__ void __launch_bounds__(256) scatter_perm()
{
    cudaGridDependencySynchronize();       // wait for scan_hist's writes

    const int qi = blockIdx.x * blockDim.x + threadIdx.x;

    const int v = g_vidx[qi];
    const int r = g_rank[qi];
    const int bin = (v >= 0) ? (v >> BUCKET_SHIFT) : (NBINS - 1);
    const int pos = __ldg(&g_off[bin]) + r;   // off[] is L2-resident
    g_sorted[pos] = make_int2(qi, v);

    cudaTriggerProgrammaticLaunchCompletion();
}

// Full-occupancy gather: warp-per-row, 6 independent float4 loads, __stcs.
__global__ void __launch_bounds__(THREADS) gather_phase(
    const float4* __restrict__ voxel_features,  // [total_voxels, 192] as float4
    float4* __restrict__ out)                   // [M, 192] as float4
{
    cudaGridDependencySynchronize();       // wait for scatter's writes

    const int warp = threadIdx.x >> 5;
    const int lane = threadIdx.x & 31;
    const int wi   = blockIdx.x * (THREADS / 32) + warp;

    const int2 s = __ldg(&g_sorted[wi]);   // one load: {qi, vidx}
    const int qi = s.x;
    const int v  = s.y;

    const float4* src = voxel_features + (size_t)v * VEC4_PER_ROW + lane;
    float4*       dst = out            + (size_t)qi * VEC4_PER_ROW + lane;

    float4 r[V4_PER_LANE];
    if (v >= 0) {
        #pragma unroll
        for (int i = 0; i < V4_PER_LANE; i++)   // 6 loads in flight (MLP=6)
            r[i] = __ldg(src + 32 * i);
    } else {
        #pragma unroll
        for (int i = 0; i < V4_PER_LANE; i++)
            r[i] = make_float4(0.f, 0.f, 0.f, 0.f);
    }

    // Streaming stores: output never re-read; keep L2 for feature rows.
    #pragma unroll
    for (int i = 0; i < V4_PER_LANE; i++)
        __stcs(dst + 32 * i, r[i]);
}

// Launch helper: programmatic stream serialization (PDL) on downstream kernels.
template <typename... Args>
static void launch_pdl(void (*kernel)(Args...), dim3 grid, dim3 block, Args... args)
{
    cudaLaunchConfig_t cfg = {};
    cfg.gridDim  = grid;
    cfg.blockDim = block;
    cfg.dynamicSmemBytes = 0;
    cfg.stream = 0;
    cudaLaunchAttribute attr[1];
    attr[0].id = cudaLaunchAttributeProgrammaticStreamSerialization;
    attr[0].val.programmaticStreamSerializationAllowed = 1;
    cfg.attrs = attr;
    cfg.numAttrs = 1;
    cudaLaunchKernelEx(&cfg, kernel, args...);
}

extern "C" void kernel_launch(void* const* d_in, const int* in_sizes, int n_in,
                              void* d_out, int out_size)
{
    const float*  query_pts = (const float*)d_in[0];
    const float4* feats     = (const float4*)d_in[1];
    const int*    buf       = (const int*)d_in[2];
    float4*       out       = (float4*)d_out;

    const int M = in_sizes[0] / 3;                  // 262144
    const int total_voxels = in_sizes[1] / FEATURE_DIM;

    // hash_hist: NORMAL launch -> serializes against prior replay's gather
    // before scratch buffers are overwritten.
    hash_hist<<<M / 256, 256>>>(query_pts, buf, total_voxels);

    launch_pdl(scan_hist, dim3(1), dim3(1024));
    launch_pdl(scatter_perm, dim3(M / 256), dim3(256));
    launch_pdl(gather_phase, dim3(M / (THREADS / 32)), dim3(THREADS),
               feats, out);
}